// round 5
// baseline (speedup 1.0000x reference)
#include <cuda_runtime.h>
#include <math.h>

#define EPSV 1e-7f

// ---- problem sizes (fixed by the dataset) ----
#define NB 4
#define H0 256
#define W0 448
#define HW0 (H0*W0)      // 114688
#define H1 128
#define W1 224
#define HW1 (H1*W1)      // 28672
#define H2 64
#define W2 112
#define HW2 (H2*W2)      // 7168
#define C0 32
#define C1 64
#define C2 96

// padded NHWC pixel strides (floats): C feats + den + hole, padded to
// a multiple of 8 floats (32B) so every v4 RED stays inside ONE 32B L2
// sector (16-mod-32 bases straddle sectors and double the RMW cost).
#define S0 40
#define S1 72
#define S2 104
#define SF 8

// ---- scratch layout (floats) ----
#define OFF_ACC0  0
#define OFF_ACC1  (OFF_ACC0 + NB*HW0*S0)
#define OFF_ACC2  (OFF_ACC1 + NB*HW1*S1)
#define OFF_ACCF  (OFF_ACC2 + NB*HW2*S2)
#define OFF_FLOW1 (OFF_ACCF + NB*HW0*SF)
#define OFF_MET1  (OFF_FLOW1 + NB*2*HW1)
#define OFF_FLOW2 (OFF_MET1 + NB*HW1)
#define OFF_MET2  (OFF_FLOW2 + NB*2*HW2)
#define SCRATCH_TOTAL (OFF_MET2 + NB*HW2)
#define ACC_TOTAL OFF_FLOW1

__device__ __align__(256) float g_scratch[SCRATCH_TOTAL];

__device__ __forceinline__ void red_add_v4(float* p, float a, float b, float c, float d) {
    asm volatile("red.global.add.v4.f32 [%0], {%1,%2,%3,%4};"
                 :: "l"(p), "f"(a), "f"(b), "f"(c), "f"(d) : "memory");
}
__device__ __forceinline__ void red_add_v2(float* p, float a, float b) {
    asm volatile("red.global.add.v2.f32 [%0], {%1,%2};"
                 :: "l"(p), "f"(a), "f"(b) : "memory");
}

// ---- 2x antialiased bilinear downsample (jax.image.resize, antialias=True) ----
template<int Hi, int Wi>
__global__ __launch_bounds__(256) void resize_half_kernel(
    const float* __restrict__ src_flow,
    const float* __restrict__ src_met,
    float* __restrict__ dst_flow,
    float* __restrict__ dst_met,
    float flow_scale)
{
    const int Ho = Hi / 2, Wo = Wi / 2;
    int i = blockIdx.x * blockDim.x + threadIdx.x;
    int total = NB * 3 * Ho * Wo;
    if (i >= total) return;
    int p  = i % (Ho * Wo);
    int nc = i / (Ho * Wo);
    int c  = nc % 3;
    int n  = nc / 3;
    int oy = p / Wo, ox = p % Wo;

    const float raw[4] = {0.25f, 0.75f, 0.75f, 0.25f};
    float wy[4], wx[4];
    int   jy[4], jx[4];
    float sy = 0.f, sx = 0.f;
#pragma unroll
    for (int k = 0; k < 4; k++) {
        int j = 2 * oy - 1 + k;
        float w = (j >= 0 && j < Hi) ? raw[k] : 0.f;
        jy[k] = min(max(j, 0), Hi - 1);
        wy[k] = w; sy += w;
    }
#pragma unroll
    for (int k = 0; k < 4; k++) {
        int j = 2 * ox - 1 + k;
        float w = (j >= 0 && j < Wi) ? raw[k] : 0.f;
        jx[k] = min(max(j, 0), Wi - 1);
        wx[k] = w; sx += w;
    }
    float inv = 1.f / (sy * sx);

    const float* src = (c < 2) ? (src_flow + ((size_t)n * 2 + c) * Hi * Wi)
                               : (src_met  + (size_t)n * Hi * Wi);
    float acc = 0.f;
#pragma unroll
    for (int ky = 0; ky < 4; ky++) {
        if (wy[ky] == 0.f) continue;
        const float* row = src + (size_t)jy[ky] * Wi;
        float a = 0.f;
#pragma unroll
        for (int kx = 0; kx < 4; kx++) a += wx[kx] * row[jx[kx]];
        acc += wy[ky] * a;
    }
    acc *= inv;

    if (c < 2) dst_flow[((size_t)n * 2 + c) * Ho * Wo + p] = acc * flow_scale;
    else       dst_met [(size_t)n * Ho * Wo + p] = acc;
}

// ---- NHWC splat with vector reductions ----
// acc layout: [NB*H*W][SP] where [0..C) feats, [C]=den, [C+1]=hole.
// Each thread handles one pixel and a group of 8 channels.
template<int C, int H, int W, int SP>
__global__ __launch_bounds__(256) void splat_nhwc_kernel(
    const float* __restrict__ feat,
    const float* __restrict__ flow,
    const float* __restrict__ metric,
    float* __restrict__ acc,
    float flow_scale)
{
    constexpr int P = NB * H * W;
    constexpr int NGRP = C / 8;
    int i = blockIdx.x * blockDim.x + threadIdx.x;
    if (i >= P * NGRP) return;
    int pix = i % P;         // warps: consecutive pixels, uniform group
    int g   = i / P;
    int n = pix / (H * W);
    int p = pix % (H * W);
    int y = p / W, x = p % W;

    const float* fl = flow + (size_t)n * 2 * H * W;
    float gx = (float)x + fl[p]         * flow_scale;
    float gy = (float)y + fl[H * W + p] * flow_scale;
    float x0f = floorf(gx), y0f = floorf(gy);
    float fx = gx - x0f, fy = gy - y0f;
    int x0 = (int)x0f, y0 = (int)y0f;

    float m = metric[(size_t)n * H * W + p];
    float e = __expf(fminf(fmaxf(-m, -20.f), 20.f));

    float w[4]  = {(1.f - fx) * (1.f - fy), fx * (1.f - fy),
                   (1.f - fx) * fy,         fx * fy};
    int   xi[2] = {x0, x0 + 1};
    int   yi[2] = {y0, y0 + 1};
    bool  vx[2] = {x0 >= 0 && x0 < W, x0 + 1 >= 0 && x0 + 1 < W};
    bool  vy[2] = {y0 >= 0 && y0 < H, y0 + 1 >= 0 && y0 + 1 < H};

    // load 8 channels, pre-scaled by e
    int c0 = g * 8;
    const float* fp = feat + (size_t)n * C * H * W + (size_t)c0 * H * W + p;
    float v[8];
#pragma unroll
    for (int j = 0; j < 8; j++) v[j] = fp[(size_t)j * H * W] * e;

#pragma unroll
    for (int ky = 0; ky < 2; ky++) {
#pragma unroll
        for (int kx = 0; kx < 2; kx++) {
            if (!(vx[kx] && vy[ky])) continue;
            float wk = w[ky * 2 + kx];
            float* base = acc + ((size_t)n * H * W + yi[ky] * W + xi[kx]) * SP;
            red_add_v4(base + c0,     wk * v[0], wk * v[1], wk * v[2], wk * v[3]);
            red_add_v4(base + c0 + 4, wk * v[4], wk * v[5], wk * v[6], wk * v[7]);
            if (g == 0) red_add_v2(base + C, wk * e, wk);
        }
    }
}

// ---- flow self-splat (Ft2), stride-8 NHWC accumulator (32B aligned) ----
__global__ __launch_bounds__(256) void splat_flow_kernel(
    const float* __restrict__ F21,
    const float* __restrict__ m2t,
    float* __restrict__ acc)
{
    constexpr int H = H0, W = W0;
    constexpr int P = NB * H * W;
    int i = blockIdx.x * blockDim.x + threadIdx.x;
    if (i >= P) return;
    int n = i / (H * W);
    int p = i % (H * W);
    int y = p / W, x = p % W;

    const float* fl = F21 + (size_t)n * 2 * H * W;
    float ux = fl[p] * 0.5f;           // F2t = 0.5*F21
    float uy = fl[H * W + p] * 0.5f;
    float gx = (float)x + ux;
    float gy = (float)y + uy;
    float x0f = floorf(gx), y0f = floorf(gy);
    float fx = gx - x0f, fy = gy - y0f;
    int x0 = (int)x0f, y0 = (int)y0f;

    float m = m2t[(size_t)n * H * W + p];
    float e = __expf(fminf(fmaxf(-m, -20.f), 20.f));
    float vx0 = ux * e, vy0 = uy * e;

    float w[4]  = {(1.f - fx) * (1.f - fy), fx * (1.f - fy),
                   (1.f - fx) * fy,         fx * fy};
    int   xi[2] = {x0, x0 + 1};
    int   yi[2] = {y0, y0 + 1};
    bool  bx[2] = {x0 >= 0 && x0 < W, x0 + 1 >= 0 && x0 + 1 < W};
    bool  by[2] = {y0 >= 0 && y0 < H, y0 + 1 >= 0 && y0 + 1 < H};

#pragma unroll
    for (int ky = 0; ky < 2; ky++) {
#pragma unroll
        for (int kx = 0; kx < 2; kx++) {
            if (!(bx[kx] && by[ky])) continue;
            float wk = w[ky * 2 + kx];
            float* base = acc + ((size_t)n * H * W + yi[ky] * W + xi[kx]) * SF;
            red_add_v4(base, wk * vx0, wk * vy0, wk * e, 0.f);
        }
    }
}

// ---- normalize + NHWC->NCHW transpose + hole binarize ----
// TP=64 pixels/block; smem pixel stride padded to odd (SP+1) -> transpose
// reads hit all 32 banks.
template<int C, int H, int W, int SP>
__global__ __launch_bounds__(256) void norm_transpose_kernel(
    const float* __restrict__ acc,
    float* __restrict__ out,
    float* __restrict__ bm)
{
    constexpr int TP = 64;
    constexpr int SPAD = SP + 1;           // odd -> gcd(SPAD,32)=1
    __shared__ float tile[TP * SPAD];
    __shared__ float inv[TP];

    int gp0 = blockIdx.x * TP;             // global pixel base (n*HW+p)
    const float* src = acc + (size_t)gp0 * SP;
    for (int j = threadIdx.x; j < TP * SP; j += 256) {
        int pl = j / SP;
        int k  = j - pl * SP;
        tile[pl * SPAD + k] = src[j];
    }
    __syncthreads();
    if (threadIdx.x < TP)
        inv[threadIdx.x] = 1.f / (tile[threadIdx.x * SPAD + C] + EPSV);
    __syncthreads();

    int n  = gp0 / (H * W);
    int p0 = gp0 % (H * W);
    float* outn = out + (size_t)n * C * H * W;
    for (int j = threadIdx.x; j < C * TP; j += 256) {
        int pl = j & (TP - 1);
        int c  = j >> 6;                   // log2(TP)
        outn[(size_t)c * H * W + p0 + pl] = tile[pl * SPAD + c] * inv[pl];
    }
    if (threadIdx.x < TP) {
        float h = tile[threadIdx.x * SPAD + C + 1];
        float r = h / (h + EPSV);
        bm[(size_t)gp0 + threadIdx.x] = (r <= 0.5f) ? 1.f : 0.f;
    }
}

// ---- normalize Ft2: ft2 = -num/(den+eps) ----
__global__ __launch_bounds__(256) void norm_flow_kernel(
    const float* __restrict__ acc,
    float* __restrict__ ft2)
{
    constexpr int P = NB * HW0;
    int i = blockIdx.x * blockDim.x + threadIdx.x;
    if (i >= P) return;
    float4 a = *reinterpret_cast<const float4*>(acc + (size_t)i * SF);
    float inv = 1.f / (a.z + EPSV);
    int n = i / HW0;
    int p = i % HW0;
    float* dst = ft2 + (size_t)n * 2 * HW0;
    dst[p]       = -a.x * inv;
    dst[HW0 + p] = -a.y * inv;
}

extern "C" void kernel_launch(void* const* d_in, const int* in_sizes, int n_in,
                              void* d_out, int out_size)
{
    // metadata order: 0:x1_0 1:x2_0 2:x1_1 3:x2_1 4:x1_2 5:x2_2 6:m1t 7:m2t 8:F12 9:F21
    const float* x1_0 = (const float*)d_in[0];
    const float* x1_1 = (const float*)d_in[2];
    const float* x1_2 = (const float*)d_in[4];
    const float* m1t = (const float*)d_in[6];
    const float* m2t = (const float*)d_in[7];
    const float* F12 = (const float*)d_in[8];
    const float* F21 = (const float*)d_in[9];

    float* out = (float*)d_out;
    float* w0  = out;
    float* w1  = w0 + (size_t)NB * C0 * HW0;
    float* w2  = w1 + (size_t)NB * C1 * HW1;
    float* bm0 = w2 + (size_t)NB * C2 * HW2;
    float* bm1 = bm0 + (size_t)NB * HW0;
    float* bm2 = bm1 + (size_t)NB * HW1;
    float* ft2 = bm2 + (size_t)NB * HW2;

    float* scratch = nullptr;
    cudaGetSymbolAddress((void**)&scratch, g_scratch);
    float* acc0  = scratch + OFF_ACC0;
    float* acc1  = scratch + OFF_ACC1;
    float* acc2  = scratch + OFF_ACC2;
    float* accF  = scratch + OFF_ACCF;
    float* flow1 = scratch + OFF_FLOW1;
    float* met1  = scratch + OFF_MET1;
    float* flow2 = scratch + OFF_FLOW2;
    float* met2  = scratch + OFF_MET2;

    const int TB = 256;

    // zero the NHWC accumulators
    cudaMemsetAsync(scratch, 0, (size_t)ACC_TOTAL * sizeof(float), 0);

    // chained antialiased 2x downsamples of (flow, metric)
    {
        int total = NB * 3 * HW1;
        resize_half_kernel<H0, W0><<<(total + TB - 1) / TB, TB>>>(
            F12, m1t, flow1, met1, 0.25f);
    }
    {
        int total = NB * 3 * HW2;
        resize_half_kernel<H1, W1><<<(total + TB - 1) / TB, TB>>>(
            flow1, met1, flow2, met2, 0.5f);
    }

    // splats (NHWC accumulation, vector reds, 32B-aligned pixel strides)
    {
        int total = NB * HW0 * (C0 / 8);
        splat_nhwc_kernel<C0, H0, W0, S0><<<(total + TB - 1) / TB, TB>>>(
            x1_0, F12, m1t, acc0, 0.5f);
    }
    {
        int total = NB * HW1 * (C1 / 8);
        splat_nhwc_kernel<C1, H1, W1, S1><<<(total + TB - 1) / TB, TB>>>(
            x1_1, flow1, met1, acc1, 1.0f);
    }
    {
        int total = NB * HW2 * (C2 / 8);
        splat_nhwc_kernel<C2, H2, W2, S2><<<(total + TB - 1) / TB, TB>>>(
            x1_2, flow2, met2, acc2, 1.0f);
    }
    {
        int total = NB * HW0;
        splat_flow_kernel<<<(total + TB - 1) / TB, TB>>>(F21, m2t, accF);
    }

    // normalize + transpose + binarize
    norm_transpose_kernel<C0, H0, W0, S0><<<NB * HW0 / 64, TB>>>(acc0, w0, bm0);
    norm_transpose_kernel<C1, H1, W1, S1><<<NB * HW1 / 64, TB>>>(acc1, w1, bm1);
    norm_transpose_kernel<C2, H2, W2, S2><<<NB * HW2 / 64, TB>>>(acc2, w2, bm2);
    norm_flow_kernel<<<(NB * HW0 + TB - 1) / TB, TB>>>(accF, ft2);
}

// round 6
// speedup vs baseline: 1.5855x; 1.5855x over previous
#include <cuda_runtime.h>
#include <cuda_fp16.h>
#include <math.h>

#define EPSV 1e-7f

// ---- problem sizes (fixed by the dataset) ----
#define NB 4
#define H0 256
#define W0 448
#define HW0 (H0*W0)      // 114688
#define H1 128
#define W1 224
#define HW1 (H1*W1)      // 28672
#define H2 64
#define W2 112
#define HW2 (H2*W2)      // 7168
#define C0 32
#define C1 64
#define C2 96

// NHWC accumulator pixel strides in u32 units:
//   [0 .. C/2)  : C channels as f16x2 (channel pair (2c,2c+1) per u32)
//   [C/2]       : den  (f32)
//   [C/2+1]     : hole (f32)
//   padded to a multiple of 4 u32 (16B) for v4 RED alignment
#define S0 20
#define S1 36
#define S2 52
#define SF 4             // flow acc: 4 f32 (vx, vy, den, pad)

// ---- scratch layout (u32 units) ----
#define OFF_ACC0  0
#define OFF_ACC1  (OFF_ACC0 + NB*HW0*S0)
#define OFF_ACC2  (OFF_ACC1 + NB*HW1*S1)
#define OFF_ACCF  (OFF_ACC2 + NB*HW2*S2)
#define OFF_FLOW1 (OFF_ACCF + NB*HW0*SF)
#define OFF_MET1  (OFF_FLOW1 + NB*2*HW1)
#define OFF_FLOW2 (OFF_MET1 + NB*HW1)
#define OFF_MET2  (OFF_FLOW2 + NB*2*HW2)
#define SCRATCH_TOTAL (OFF_MET2 + NB*HW2)
#define ACC_TOTAL OFF_FLOW1

__device__ __align__(256) unsigned g_scratch[SCRATCH_TOTAL];

__device__ __forceinline__ void red_add_v4_f32(float* p, float a, float b, float c, float d) {
    asm volatile("red.global.add.v4.f32 [%0], {%1,%2,%3,%4};"
                 :: "l"(p), "f"(a), "f"(b), "f"(c), "f"(d) : "memory");
}
__device__ __forceinline__ void red_add_v2_f32(float* p, float a, float b) {
    asm volatile("red.global.add.v2.f32 [%0], {%1,%2};"
                 :: "l"(p), "f"(a), "f"(b) : "memory");
}
__device__ __forceinline__ void red_add_v4_h2(unsigned* p, unsigned a, unsigned b,
                                              unsigned c, unsigned d) {
    asm volatile("red.global.add.noftz.v4.f16x2 [%0], {%1,%2,%3,%4};"
                 :: "l"(p), "r"(a), "r"(b), "r"(c), "r"(d) : "memory");
}
__device__ __forceinline__ unsigned pack_h2(float lo, float hi) {
    __half2 h = __floats2half2_rn(lo, hi);   // lo -> .x (low half)
    return *reinterpret_cast<unsigned*>(&h);
}

// ---- 2x antialiased bilinear downsample (jax.image.resize, antialias=True) ----
template<int Hi, int Wi>
__global__ __launch_bounds__(256) void resize_half_kernel(
    const float* __restrict__ src_flow,
    const float* __restrict__ src_met,
    float* __restrict__ dst_flow,
    float* __restrict__ dst_met,
    float flow_scale)
{
    const int Ho = Hi / 2, Wo = Wi / 2;
    int i = blockIdx.x * blockDim.x + threadIdx.x;
    int total = NB * 3 * Ho * Wo;
    if (i >= total) return;
    int p  = i % (Ho * Wo);
    int nc = i / (Ho * Wo);
    int c  = nc % 3;
    int n  = nc / 3;
    int oy = p / Wo, ox = p % Wo;

    const float raw[4] = {0.25f, 0.75f, 0.75f, 0.25f};
    float wy[4], wx[4];
    int   jy[4], jx[4];
    float sy = 0.f, sx = 0.f;
#pragma unroll
    for (int k = 0; k < 4; k++) {
        int j = 2 * oy - 1 + k;
        float w = (j >= 0 && j < Hi) ? raw[k] : 0.f;
        jy[k] = min(max(j, 0), Hi - 1);
        wy[k] = w; sy += w;
    }
#pragma unroll
    for (int k = 0; k < 4; k++) {
        int j = 2 * ox - 1 + k;
        float w = (j >= 0 && j < Wi) ? raw[k] : 0.f;
        jx[k] = min(max(j, 0), Wi - 1);
        wx[k] = w; sx += w;
    }
    float inv = 1.f / (sy * sx);

    const float* src = (c < 2) ? (src_flow + ((size_t)n * 2 + c) * Hi * Wi)
                               : (src_met  + (size_t)n * Hi * Wi);
    float acc = 0.f;
#pragma unroll
    for (int ky = 0; ky < 4; ky++) {
        if (wy[ky] == 0.f) continue;
        const float* row = src + (size_t)jy[ky] * Wi;
        float a = 0.f;
#pragma unroll
        for (int kx = 0; kx < 4; kx++) a += wx[kx] * row[jx[kx]];
        acc += wy[ky] * a;
    }
    acc *= inv;

    if (c < 2) dst_flow[((size_t)n * 2 + c) * Ho * Wo + p] = acc * flow_scale;
    else       dst_met [(size_t)n * Ho * Wo + p] = acc;
}

// ---- NHWC splat: f16x2 feature accumulation, f32 den/hole ----
// Each thread handles one pixel and a group of 16 channels.
template<int C, int H, int W, int SP>
__global__ __launch_bounds__(256) void splat_half_kernel(
    const float* __restrict__ feat,
    const float* __restrict__ flow,
    const float* __restrict__ metric,
    unsigned* __restrict__ acc,
    float flow_scale)
{
    constexpr int P = NB * H * W;
    constexpr int NGRP = C / 16;
    int i = blockIdx.x * blockDim.x + threadIdx.x;
    if (i >= P * NGRP) return;
    int pix = i % P;          // warps: consecutive pixels, uniform group
    int g   = i / P;
    int n = pix / (H * W);
    int p = pix % (H * W);
    int y = p / W, x = p % W;

    const float* fl = flow + (size_t)n * 2 * H * W;
    float gx = (float)x + fl[p]         * flow_scale;
    float gy = (float)y + fl[H * W + p] * flow_scale;
    float x0f = floorf(gx), y0f = floorf(gy);
    float fx = gx - x0f, fy = gy - y0f;
    int x0 = (int)x0f, y0 = (int)y0f;

    float m = metric[(size_t)n * H * W + p];
    float e = __expf(fminf(fmaxf(-m, -20.f), 20.f));

    float w[4]  = {(1.f - fx) * (1.f - fy), fx * (1.f - fy),
                   (1.f - fx) * fy,         fx * fy};
    int   xi[2] = {x0, x0 + 1};
    int   yi[2] = {y0, y0 + 1};
    bool  vx[2] = {x0 >= 0 && x0 < W, x0 + 1 >= 0 && x0 + 1 < W};
    bool  vy[2] = {y0 >= 0 && y0 < H, y0 + 1 >= 0 && y0 + 1 < H};

    // load 16 channels, pre-scaled by e (f32)
    int c0 = g * 16;
    const float* fp = feat + (size_t)n * C * H * W + (size_t)c0 * H * W + p;
    float v[16];
#pragma unroll
    for (int j = 0; j < 16; j++) v[j] = fp[(size_t)j * H * W] * e;

#pragma unroll
    for (int ky = 0; ky < 2; ky++) {
#pragma unroll
        for (int kx = 0; kx < 2; kx++) {
            if (!(vx[kx] && vy[ky])) continue;
            float wk = w[ky * 2 + kx];
            unsigned* pixbase = acc + ((size_t)n * H * W + yi[ky] * W + xi[kx]) * SP;
            unsigned pk[8];
#pragma unroll
            for (int j = 0; j < 8; j++)
                pk[j] = pack_h2(wk * v[2 * j], wk * v[2 * j + 1]);
            unsigned* fb = pixbase + (c0 >> 1);
            red_add_v4_h2(fb,     pk[0], pk[1], pk[2], pk[3]);
            red_add_v4_h2(fb + 4, pk[4], pk[5], pk[6], pk[7]);
            if (g == 0)
                red_add_v2_f32(reinterpret_cast<float*>(pixbase + (C >> 1)),
                               wk * e, wk);
        }
    }
}

// ---- flow self-splat (Ft2), f32 v4 accumulator ----
__global__ __launch_bounds__(256) void splat_flow_kernel(
    const float* __restrict__ F21,
    const float* __restrict__ m2t,
    float* __restrict__ acc)
{
    constexpr int H = H0, W = W0;
    constexpr int P = NB * H * W;
    int i = blockIdx.x * blockDim.x + threadIdx.x;
    if (i >= P) return;
    int n = i / (H * W);
    int p = i % (H * W);
    int y = p / W, x = p % W;

    const float* fl = F21 + (size_t)n * 2 * H * W;
    float ux = fl[p] * 0.5f;           // F2t = 0.5*F21
    float uy = fl[H * W + p] * 0.5f;
    float gx = (float)x + ux;
    float gy = (float)y + uy;
    float x0f = floorf(gx), y0f = floorf(gy);
    float fx = gx - x0f, fy = gy - y0f;
    int x0 = (int)x0f, y0 = (int)y0f;

    float m = m2t[(size_t)n * H * W + p];
    float e = __expf(fminf(fmaxf(-m, -20.f), 20.f));
    float vx0 = ux * e, vy0 = uy * e;

    float w[4]  = {(1.f - fx) * (1.f - fy), fx * (1.f - fy),
                   (1.f - fx) * fy,         fx * fy};
    int   xi[2] = {x0, x0 + 1};
    int   yi[2] = {y0, y0 + 1};
    bool  bx[2] = {x0 >= 0 && x0 < W, x0 + 1 >= 0 && x0 + 1 < W};
    bool  by[2] = {y0 >= 0 && y0 < H, y0 + 1 >= 0 && y0 + 1 < H};

#pragma unroll
    for (int ky = 0; ky < 2; ky++) {
#pragma unroll
        for (int kx = 0; kx < 2; kx++) {
            if (!(bx[kx] && by[ky])) continue;
            float wk = w[ky * 2 + kx];
            float* base = acc + ((size_t)n * H * W + yi[ky] * W + xi[kx]) * SF;
            red_add_v4_f32(base, wk * vx0, wk * vy0, wk * e, 0.f);
        }
    }
}

// ---- normalize + f16->f32 + NHWC->NCHW transpose + hole binarize ----
// TP=32 pixels/block; smem pixel stride padded to odd -> conflict-free.
template<int C, int H, int W, int SP>
__global__ __launch_bounds__(256) void norm_transpose_kernel(
    const unsigned* __restrict__ acc,
    float* __restrict__ out,
    float* __restrict__ bm)
{
    constexpr int TP = 32;
    constexpr int SPAD = SP + 1;           // odd -> gcd(SPAD,32)=1
    __shared__ unsigned tile[TP * SPAD];
    __shared__ float inv[TP];

    int gp0 = blockIdx.x * TP;             // global pixel base (n*HW+p)
    const unsigned* src = acc + (size_t)gp0 * SP;
    for (int j = threadIdx.x; j < TP * SP; j += 256) {
        int pl = j / SP;
        int k  = j - pl * SP;
        tile[pl * SPAD + k] = src[j];
    }
    __syncthreads();
    if (threadIdx.x < TP)
        inv[threadIdx.x] =
            1.f / (__uint_as_float(tile[threadIdx.x * SPAD + (C >> 1)]) + EPSV);
    __syncthreads();

    int n  = gp0 / (H * W);
    int p0 = gp0 % (H * W);
    float* outn = out + (size_t)n * C * H * W;
    for (int j = threadIdx.x; j < C * TP; j += 256) {
        int pl = j & 31;
        int c  = j >> 5;
        unsigned u = tile[pl * SPAD + (c >> 1)];
        __half2 h2 = *reinterpret_cast<__half2*>(&u);
        float vv = (c & 1) ? __high2float(h2) : __low2float(h2);
        outn[(size_t)c * H * W + p0 + pl] = vv * inv[pl];
    }
    if (threadIdx.x < TP) {
        float h = __uint_as_float(tile[threadIdx.x * SPAD + (C >> 1) + 1]);
        float r = h / (h + EPSV);
        bm[(size_t)gp0 + threadIdx.x] = (r <= 0.5f) ? 1.f : 0.f;
    }
}

// ---- normalize Ft2: ft2 = -num/(den+eps) ----
__global__ __launch_bounds__(256) void norm_flow_kernel(
    const float* __restrict__ acc,
    float* __restrict__ ft2)
{
    constexpr int P = NB * HW0;
    int i = blockIdx.x * blockDim.x + threadIdx.x;
    if (i >= P) return;
    float4 a = *reinterpret_cast<const float4*>(acc + (size_t)i * SF);
    float inv = 1.f / (a.z + EPSV);
    int n = i / HW0;
    int p = i % HW0;
    float* dst = ft2 + (size_t)n * 2 * HW0;
    dst[p]       = -a.x * inv;
    dst[HW0 + p] = -a.y * inv;
}

extern "C" void kernel_launch(void* const* d_in, const int* in_sizes, int n_in,
                              void* d_out, int out_size)
{
    // metadata order: 0:x1_0 1:x2_0 2:x1_1 3:x2_1 4:x1_2 5:x2_2 6:m1t 7:m2t 8:F12 9:F21
    const float* x1_0 = (const float*)d_in[0];
    const float* x1_1 = (const float*)d_in[2];
    const float* x1_2 = (const float*)d_in[4];
    const float* m1t = (const float*)d_in[6];
    const float* m2t = (const float*)d_in[7];
    const float* F12 = (const float*)d_in[8];
    const float* F21 = (const float*)d_in[9];

    float* out = (float*)d_out;
    float* w0  = out;
    float* w1  = w0 + (size_t)NB * C0 * HW0;
    float* w2  = w1 + (size_t)NB * C1 * HW1;
    float* bm0 = w2 + (size_t)NB * C2 * HW2;
    float* bm1 = bm0 + (size_t)NB * HW0;
    float* bm2 = bm1 + (size_t)NB * HW1;
    float* ft2 = bm2 + (size_t)NB * HW2;

    unsigned* scratch = nullptr;
    cudaGetSymbolAddress((void**)&scratch, g_scratch);
    unsigned* acc0 = scratch + OFF_ACC0;
    unsigned* acc1 = scratch + OFF_ACC1;
    unsigned* acc2 = scratch + OFF_ACC2;
    float* accF  = reinterpret_cast<float*>(scratch + OFF_ACCF);
    float* flow1 = reinterpret_cast<float*>(scratch + OFF_FLOW1);
    float* met1  = reinterpret_cast<float*>(scratch + OFF_MET1);
    float* flow2 = reinterpret_cast<float*>(scratch + OFF_FLOW2);
    float* met2  = reinterpret_cast<float*>(scratch + OFF_MET2);

    const int TB = 256;

    // zero the accumulators (f16 zero == 0x0000)
    cudaMemsetAsync(scratch, 0, (size_t)ACC_TOTAL * sizeof(unsigned), 0);

    // chained antialiased 2x downsamples of (flow, metric)
    {
        int total = NB * 3 * HW1;
        resize_half_kernel<H0, W0><<<(total + TB - 1) / TB, TB>>>(
            F12, m1t, flow1, met1, 0.25f);
    }
    {
        int total = NB * 3 * HW2;
        resize_half_kernel<H1, W1><<<(total + TB - 1) / TB, TB>>>(
            flow1, met1, flow2, met2, 0.5f);
    }

    // splats (f16x2 feature REDs, f32 den/hole REDs)
    {
        int total = NB * HW0 * (C0 / 16);
        splat_half_kernel<C0, H0, W0, S0><<<(total + TB - 1) / TB, TB>>>(
            x1_0, F12, m1t, acc0, 0.5f);
    }
    {
        int total = NB * HW1 * (C1 / 16);
        splat_half_kernel<C1, H1, W1, S1><<<(total + TB - 1) / TB, TB>>>(
            x1_1, flow1, met1, acc1, 1.0f);
    }
    {
        int total = NB * HW2 * (C2 / 16);
        splat_half_kernel<C2, H2, W2, S2><<<(total + TB - 1) / TB, TB>>>(
            x1_2, flow2, met2, acc2, 1.0f);
    }
    {
        int total = NB * HW0;
        splat_flow_kernel<<<(total + TB - 1) / TB, TB>>>(F21, m2t, accF);
    }

    // normalize + transpose + binarize
    norm_transpose_kernel<C0, H0, W0, S0><<<NB * HW0 / 32, TB>>>(acc0, w0, bm0);
    norm_transpose_kernel<C1, H1, W1, S1><<<NB * HW1 / 32, TB>>>(acc1, w1, bm1);
    norm_transpose_kernel<C2, H2, W2, S2><<<NB * HW2 / 32, TB>>>(acc2, w2, bm2);
    norm_flow_kernel<<<(NB * HW0 + TB - 1) / TB, TB>>>(accF, ft2);
}